// round 13
// baseline (speedup 1.0000x reference)
#include <cuda_runtime.h>
#include <cuda_fp16.h>

#define Bn 16
#define Cn 512
#define Sn 1024

// ---- scratch (no allocs allowed) ----
__device__ __half g_hn [Bn * Cn * Sn];   // [b][c][s]  (k-major for proj A)
__device__ __half g_Qt [Bn * Sn * Cn];   // [b][s][o]  (scale folded in)
__device__ __half g_Kt [Bn * Sn * Cn];   // [b][s][o]
__device__ __half g_Vt [Bn * Sn * Cn];   // [b][s][o]
__device__ __half g_Wqt[Cn * Cn];        // W^T : [out][in]
__device__ __half g_Wkt[Cn * Cn];
__device__ __half g_Wvt[Cn * Cn];
__device__ __half g_Wnt[Cn * Cn];
__device__ float  g_D  [Bn * Sn];        // diag softmax

// ---------------------------------------------------------------------------
__device__ __forceinline__ void mma_f16(unsigned c[2], const unsigned a[4],
                                        unsigned b0, unsigned b1) {
    asm volatile(
        "mma.sync.aligned.m16n8k16.row.col.f16.f16.f16.f16 "
        "{%0,%1},{%2,%3,%4,%5},{%6,%7},{%0,%1};\n"
        : "+r"(c[0]), "+r"(c[1])
        : "r"(a[0]), "r"(a[1]), "r"(a[2]), "r"(a[3]), "r"(b0), "r"(b1));
}

__device__ __forceinline__ void ldm_x4(unsigned f[4], const void* p) {
    unsigned addr = (unsigned)__cvta_generic_to_shared(p);
    asm volatile(
        "ldmatrix.sync.aligned.m8n8.x4.shared.b16 {%0,%1,%2,%3},[%4];\n"
        : "=r"(f[0]), "=r"(f[1]), "=r"(f[2]), "=r"(f[3]) : "r"(addr));
}
__device__ __forceinline__ void ldm_x4u(unsigned f[4], unsigned addr) {
    asm volatile(
        "ldmatrix.sync.aligned.m8n8.x4.shared.b16 {%0,%1,%2,%3},[%4];\n"
        : "=r"(f[0]), "=r"(f[1]), "=r"(f[2]), "=r"(f[3]) : "r"(addr));
}

__device__ __forceinline__ void cp16(void* dst, const void* src) {
    unsigned d = (unsigned)__cvta_generic_to_shared(dst);
    asm volatile("cp.async.cg.shared.global [%0], [%1], 16;\n" :: "r"(d), "l"(src));
}
__device__ __forceinline__ void cp16s(unsigned dst, const void* src) {
    asm volatile("cp.async.cg.shared.global [%0], [%1], 16;\n" :: "r"(dst), "l"(src));
}
__device__ __forceinline__ void cp_commit() {
    asm volatile("cp.async.commit_group;\n");
}
template <int N> __device__ __forceinline__ void cp_wait() {
    asm volatile("cp.async.wait_group %0;\n" :: "n"(N));
}

// ---------------------------------------------------------------------------
// Weight transpose+convert: Wt[out][in] f16 = W[in][out] fp32.
// ---------------------------------------------------------------------------
__global__ void __launch_bounds__(256) wconv_kernel(const float* __restrict__ Wq,
                                                    const float* __restrict__ Wk,
                                                    const float* __restrict__ Wv,
                                                    const float* __restrict__ Wn) {
    __shared__ float t[32][33];
    int w = blockIdx.z;
    const float* src = (w == 0) ? Wq : (w == 1) ? Wk : (w == 2) ? Wv : Wn;
    __half* dst = (w == 0) ? g_Wqt : (w == 1) ? g_Wkt : (w == 2) ? g_Wvt : g_Wnt;
    int c0 = blockIdx.x * 32, r0 = blockIdx.y * 32;
    int tx = threadIdx.x & 31, ty = threadIdx.x >> 5;
#pragma unroll
    for (int i = 0; i < 4; i++)
        t[ty + i * 8][tx] = src[(size_t)(r0 + ty + i * 8) * Cn + c0 + tx];
    __syncthreads();
#pragma unroll
    for (int i = 0; i < 4; i++)
        dst[(size_t)(c0 + ty + i * 8) * Cn + r0 + tx] = __float2half(t[tx][ty + i * 8]);
}

// ---------------------------------------------------------------------------
// GroupNorm: one block per (b, group); whole group tile in registers. -> f16
// ---------------------------------------------------------------------------
__global__ void __launch_bounds__(256) gn_kernel(const float* __restrict__ x) {
    int b = blockIdx.x >> 5, g = blockIdx.x & 31;
    size_t base = ((size_t)b * Cn + g * 16) * Sn;
    const float4* x4 = (const float4*)(x + base);
    int tid = threadIdx.x;

    float4 v[16];
    float s = 0.f, ss = 0.f;
#pragma unroll
    for (int i = 0; i < 16; i++) {
        v[i] = x4[tid + i * 256];
        s  += v[i].x + v[i].y + v[i].z + v[i].w;
        ss += v[i].x * v[i].x + v[i].y * v[i].y + v[i].z * v[i].z + v[i].w * v[i].w;
    }
    __shared__ float rs[256], rq[256];
    rs[tid] = s; rq[tid] = ss;
    __syncthreads();
    for (int off = 128; off; off >>= 1) {
        if (tid < off) { rs[tid] += rs[tid + off]; rq[tid] += rq[tid + off]; }
        __syncthreads();
    }
    const float invN = 1.f / 16384.f;
    float mean = rs[0] * invN;
    float var  = rq[0] * invN - mean * mean;
    float inv  = rsqrtf(var + 1e-5f);

    uint2* h2 = (uint2*)(g_hn + base);
#pragma unroll
    for (int i = 0; i < 16; i++) {
        __half2 p0 = __floats2half2_rn((v[i].x - mean) * inv, (v[i].y - mean) * inv);
        __half2 p1 = __floats2half2_rn((v[i].z - mean) * inv, (v[i].w - mean) * inv);
        uint2 u; u.x = *(unsigned*)&p0; u.y = *(unsigned*)&p1;
        h2[tid + i * 256] = u;
    }
}

// ---------------------------------------------------------------------------
// Fused QKV projection (HMMA): ONE block computes Q, K and V for the same
// (s0, o0) tile, sharing the A tile and A fragments. 128x64, BK=32, 8 warps.
// ---------------------------------------------------------------------------
__global__ void __launch_bounds__(256) proj_kernel(const float* __restrict__ bq,
                                                   const float* __restrict__ bk,
                                                   const float* __restrict__ bv) {
    int b = blockIdx.z;
    int s0 = blockIdx.x * 128, o0 = blockIdx.y * 64;
    const __half* A = g_hn + (size_t)b * Cn * Sn;
    const __half* Wts[3] = {g_Wqt, g_Wkt, g_Wvt};

    __shared__ __align__(16) __half As[2][32][136];     // [k][m]
    __shared__ __align__(16) __half Bs[2][3][64][40];   // [w][n][k]

    int tid = threadIdx.x, lane = tid & 31, warp = tid >> 5;
    int wm = (warp & 3) * 32, wn = (warp >> 2) * 32;

    int ra = tid >> 3, ca = (tid & 7) * 16;
    int rb = tid >> 2, cb = (tid & 3) * 8;

    int mi = lane >> 3;
    int a_kr = (lane & 7) + ((mi >> 1) << 3);
    int a_mc = (mi & 1) << 3;

    int q4 = lane >> 3, r8 = lane & 7;
    int b_ro = ((q4 >> 1) << 3) + r8, b_co = (q4 & 1) << 3;

    auto issue = [&](int c0, int st) {
        cp16(&As[st][ra][ca],     A + (size_t)(c0 + ra) * Sn + s0 + ca);
        cp16(&As[st][ra][ca + 8], A + (size_t)(c0 + ra) * Sn + s0 + ca + 8);
#pragma unroll
        for (int w = 0; w < 3; w++)
            cp16(&Bs[st][w][rb][cb], Wts[w] + (size_t)(o0 + rb) * Cn + c0 + cb);
        cp_commit();
    };
    issue(0, 0);
    issue(32, 1);

    unsigned acc[3][2][4][2] = {};
#pragma unroll 1
    for (int it = 0; it < 16; it++) {
        if (it < 14) cp_wait<1>(); else cp_wait<0>();
        __syncthreads();
        int st = it & 1;
#pragma unroll
        for (int kk = 0; kk < 32; kk += 16) {
            unsigned af[2][4];
#pragma unroll
            for (int im = 0; im < 2; im++) {
                unsigned addr = (unsigned)__cvta_generic_to_shared(
                    &As[st][kk + a_kr][wm + im * 16 + a_mc]);
                asm volatile(
                    "ldmatrix.sync.aligned.m8n8.x4.trans.shared.b16 {%0,%1,%2,%3},[%4];\n"
                    : "=r"(af[im][0]), "=r"(af[im][1]), "=r"(af[im][2]), "=r"(af[im][3])
                    : "r"(addr));
            }
#pragma unroll
            for (int w = 0; w < 3; w++) {
                unsigned bf[2][4];
#pragma unroll
                for (int jp = 0; jp < 2; jp++)
                    ldm_x4(bf[jp], &Bs[st][w][wn + jp * 16 + b_ro][kk + b_co]);
#pragma unroll
                for (int jp = 0; jp < 2; jp++)
#pragma unroll
                    for (int im = 0; im < 2; im++) {
                        mma_f16(acc[w][im][2 * jp],     af[im], bf[jp][0], bf[jp][1]);
                        mma_f16(acc[w][im][2 * jp + 1], af[im], bf[jp][2], bf[jp][3]);
                    }
            }
        }
        __syncthreads();
        if (it + 2 < 16) issue((it + 2) * 32, st);
    }

    int g = lane >> 2, t = lane & 3;
#pragma unroll
    for (int w = 0; w < 3; w++) {
        const float* bias = (w == 0) ? bq : (w == 1) ? bk : bv;
        __half* out = ((w == 0) ? g_Qt : (w == 1) ? g_Kt : g_Vt) + (size_t)b * Sn * Cn;
        const float qs = (w == 0) ? 0.04419417382415922f : 1.f;  // 512^-0.5 into Q
#pragma unroll
        for (int im = 0; im < 2; im++) {
            int m = s0 + wm + im * 16 + g;
#pragma unroll
            for (int jn = 0; jn < 4; jn++) {
                int n = o0 + wn + jn * 8 + 2 * t;
                float b0f = bias[n], b1f = bias[n + 1];
                float2 lo = __half22float2(*(__half2*)&acc[w][im][jn][0]);
                float2 hi = __half22float2(*(__half2*)&acc[w][im][jn][1]);
                __half2 v0 = __floats2half2_rn((lo.x + b0f) * qs, (lo.y + b1f) * qs);
                __half2 v1 = __floats2half2_rn((hi.x + b0f) * qs, (hi.y + b1f) * qs);
                *(unsigned*)(out + (size_t)m * Cn + n)       = *(unsigned*)&v0;
                *(unsigned*)(out + (size_t)(m + 8) * Cn + n) = *(unsigned*)&v1;
            }
        }
    }
}

// ---------------------------------------------------------------------------
// Scores + diag softmax; 256 threads, 8 warps (2m x 4n), warp tile 32x64,
// block tile 64(m) x 256(n), BK=64 double-buffered, f16 acc.
// Block (jg, ig, b): rows m=ii*32+h (q rows h*32 + ig*2+ii, ii=warp&1),
// cols n=jjL*32+H (k rows H*32 + jg*8+jjL, jjL=(warp>>1)*2+side).
// Each warp owns two 32x32 softmax groups (side 0/1); shuffle reductions.
// Dynamic smem: Q 64x72 + K 256x72 f16, 2 stages = 92160 B -> 2 CTAs/SM.
// ---------------------------------------------------------------------------
#define SC_QT (64 * 144)             // Q tile bytes per stage
#define SC_KT (256 * 144)            // K tile bytes per stage
#define SC_SMEM (2 * (SC_QT + SC_KT))

__global__ void __launch_bounds__(256, 2) scores_kernel() {
    extern __shared__ char dsm_raw[];
    unsigned base_u = (unsigned)__cvta_generic_to_shared(dsm_raw);
    unsigned qbase = base_u;                 // [2][64][72]
    unsigned kbase = base_u + 2 * SC_QT;     // [2][256][72]

    int b = blockIdx.z, ig = blockIdx.y, jg = blockIdx.x;
    int tid = threadIdx.x, lane = tid & 31, warp = tid >> 5;
    int ii = warp & 1, wj = warp >> 1;
    int wm = ii * 32, wn = wj * 64;

    const __half* Qb = g_Qt + (size_t)b * Sn * Cn;
    const __half* Kb = g_Kt + (size_t)b * Sn * Cn;

    // Q loader: row rq_r = tid>>2 (0..63), 2 chunks at (tid&3)*2
    int rq_r = tid >> 2, rq_c = (tid & 3) * 2;
    int s1 = (rq_r & 31) * 32 + ig * 2 + (rq_r >> 5);
    const __half* qrow = Qb + (size_t)s1 * Cn;
    // K loader: row tid (0..255), all 8 chunks
    int s2 = (tid & 31) * 32 + jg * 8 + (tid >> 5);
    const __half* krow = Kb + (size_t)s2 * Cn;

    auto load_stage = [&](int it, int st) {
        int c0 = it * 64;
        unsigned qd = qbase + st * SC_QT + rq_r * 144 + rq_c * 16;
        cp16s(qd,      qrow + c0 + rq_c * 8);
        cp16s(qd + 16, qrow + c0 + rq_c * 8 + 8);
        unsigned kd = kbase + st * SC_KT + tid * 144;
#pragma unroll
        for (int ch = 0; ch < 8; ch++)
            cp16s(kd + ch * 16, krow + c0 + ch * 8);
        cp_commit();
    };
    load_stage(0, 0);
    load_stage(1, 1);

    // ldmatrix.x4 lane addressing ([row][k], half units)
    int q4 = lane >> 3, r8 = lane & 7;
    int a_ro = ((q4 & 1) << 3) + r8, a_co = (q4 >> 1) << 3;   // A: m-rows
    int b_ro = ((q4 >> 1) << 3) + r8, b_co = (q4 & 1) << 3;   // B: n-rows

    unsigned acc[2][8][2] = {};
#pragma unroll 1
    for (int it = 0; it < 8; it++) {
        if (it < 6) cp_wait<1>(); else cp_wait<0>();
        __syncthreads();
        int st = it & 1;
        unsigned qt = qbase + st * SC_QT;
        unsigned kt = kbase + st * SC_KT;
#pragma unroll
        for (int kk = 0; kk < 64; kk += 16) {
            unsigned af[2][4], bf[4][4];
#pragma unroll
            for (int im = 0; im < 2; im++)
                ldm_x4u(af[im], qt + (wm + im * 16 + a_ro) * 144 + (kk + a_co) * 2);
#pragma unroll
            for (int jp = 0; jp < 4; jp++)
                ldm_x4u(bf[jp], kt + (wn + jp * 16 + b_ro) * 144 + (kk + b_co) * 2);
#pragma unroll
            for (int jp = 0; jp < 4; jp++)
#pragma unroll
                for (int im = 0; im < 2; im++) {
                    mma_f16(acc[im][2 * jp],     af[im], bf[jp][0], bf[jp][1]);
                    mma_f16(acc[im][2 * jp + 1], af[im], bf[jp][2], bf[jp][3]);
                }
        }
        __syncthreads();
        if (it + 2 < 8) load_stage(it + 2, st);
    }

    // per-warp softmax over each 32x32 group (scale already folded into Q)
#pragma unroll
    for (int side = 0; side < 2; side++) {
        float mx = -1e30f;
#pragma unroll
        for (int im = 0; im < 2; im++)
#pragma unroll
            for (int j4 = 0; j4 < 4; j4++)
#pragma unroll
                for (int r = 0; r < 2; r++) {
                    float2 f = __half22float2(*(__half2*)&acc[im][side * 4 + j4][r]);
                    mx = fmaxf(mx, fmaxf(f.x, f.y));
                }
#pragma unroll
        for (int off = 16; off; off >>= 1)
            mx = fmaxf(mx, __shfl_xor_sync(0xffffffffu, mx, off));

        float se = 0.f;
#pragma unroll
        for (int im = 0; im < 2; im++)
#pragma unroll
            for (int j4 = 0; j4 < 4; j4++)
#pragma unroll
                for (int r = 0; r < 2; r++) {
                    float2 f = __half22float2(*(__half2*)&acc[im][side * 4 + j4][r]);
                    se += __expf(f.x - mx) + __expf(f.y - mx);
                }
#pragma unroll
        for (int off = 16; off; off >>= 1)
            se += __shfl_xor_sync(0xffffffffu, se, off);

        int i = ig * 2 + ii;
        int j = jg * 8 + wj * 2 + side;
        int rl = i;                    // diag row within warp tile (0..31)
        int cl = side * 32 + j;        // diag col within warp tile (0..63)
        int im_d = rl >> 4, rlow = rl & 15, reg_d = rlow >> 3, g_d = rlow & 7;
        int jn_d = cl >> 3, t_d = (cl & 7) >> 1, par = cl & 1;
        float cand = 0.f;
#pragma unroll
        for (int im = 0; im < 2; im++)
#pragma unroll
            for (int jn = 0; jn < 8; jn++)
#pragma unroll
                for (int r = 0; r < 2; r++)
                    if (im == im_d && jn == jn_d && r == reg_d) {
                        float2 f = __half22float2(*(__half2*)&acc[im][jn][r]);
                        cand = par ? f.y : f.x;
                    }
        float dv = __shfl_sync(0xffffffffu, cand, g_d * 4 + t_d);
        if (lane == 0)
            g_D[b * Sn + i * 32 + j] = __expf(dv - mx) / se;
    }
}

// ---------------------------------------------------------------------------
// Final GEMM (HMMA), f16 acc, BK=64:
// out[b][c][s] = x + D[b][s]*(sum_o Wn[o][c]*Vt[b][s][o]) + bn[c]
// ---------------------------------------------------------------------------
__global__ void __launch_bounds__(256) final_kernel(const float* __restrict__ x,
                                                    const float* __restrict__ bn,
                                                    float* __restrict__ out) {
    int b = blockIdx.z, m0 = blockIdx.x * 128, n0 = blockIdx.y * 64;
    const __half* Bsrc = g_Vt + (size_t)b * Sn * Cn;

    __shared__ __align__(16) __half As[2][128][72];  // [m][k]
    __shared__ __align__(16) __half Bs[2][64][72];   // [n][k]
    __shared__ float Ds[64];

    int tid = threadIdx.x, lane = tid & 31, warp = tid >> 5;
    int wm = (warp & 3) * 32, wn = (warp >> 2) * 32;

    int ra = tid >> 1, ca = (tid & 1) * 32;
    int rb = tid >> 2, cb = (tid & 3) * 16;

    int q4 = lane >> 3, r8 = lane & 7;
    int a_ro = ((q4 & 1) << 3) + r8, a_co = (q4 >> 1) << 3;
    int b_ro = ((q4 >> 1) << 3) + r8, b_co = (q4 & 1) << 3;

    if (tid < 64) Ds[tid] = g_D[b * Sn + n0 + tid];

    auto issue = [&](int c0, int st) {
        const __half* ar = g_Wnt + (size_t)(m0 + ra) * Cn + c0 + ca;
        cp16(&As[st][ra][ca],      ar);
        cp16(&As[st][ra][ca + 8],  ar + 8);
        cp16(&As[st][ra][ca + 16], ar + 16);
        cp16(&As[st][ra][ca + 24], ar + 24);
        const __half* br = Bsrc + (size_t)(n0 + rb) * Cn + c0 + cb;
        cp16(&Bs[st][rb][cb],     br);
        cp16(&Bs[st][rb][cb + 8], br + 8);
        cp_commit();
    };
    issue(0, 0);
    issue(64, 1);

    unsigned acc[2][4][2] = {};
#pragma unroll 1
    for (int it = 0; it < 8; it++) {
        if (it < 6) cp_wait<1>(); else cp_wait<0>();
        __syncthreads();
        int st = it & 1;
#pragma unroll
        for (int kk = 0; kk < 64; kk += 16) {
            unsigned af[2][4], bf[2][4];
#pragma unroll
            for (int im = 0; im < 2; im++)
                ldm_x4(af[im], &As[st][wm + im * 16 + a_ro][kk + a_co]);
#pragma unroll
            for (int jp = 0; jp < 2; jp++)
                ldm_x4(bf[jp], &Bs[st][wn + jp * 16 + b_ro][kk + b_co]);
#pragma unroll
            for (int jp = 0; jp < 2; jp++)
#pragma unroll
                for (int im = 0; im < 2; im++) {
                    mma_f16(acc[im][2 * jp],     af[im], bf[jp][0], bf[jp][1]);
                    mma_f16(acc[im][2 * jp + 1], af[im], bf[jp][2], bf[jp][3]);
                }
        }
        __syncthreads();
        if (it + 2 < 8) issue((it + 2) * 64, st);
    }

    int g = lane >> 2, t = lane & 3;
#pragma unroll
    for (int im = 0; im < 2; im++) {
        int m = m0 + wm + im * 16 + g;
        float bb0 = bn[m], bb1 = bn[m + 8];
#pragma unroll
        for (int jn = 0; jn < 4; jn++) {
            int n = n0 + wn + jn * 8 + 2 * t;
            float d0 = Ds[n - n0], d1 = Ds[n - n0 + 1];
            float2 lo = __half22float2(*(__half2*)&acc[im][jn][0]);
            float2 hi = __half22float2(*(__half2*)&acc[im][jn][1]);
            size_t idx = ((size_t)b * Cn + m) * Sn + n;
            float2 xr = *(const float2*)(x + idx);
            float2 o0v = {xr.x + d0 * lo.x + bb0, xr.y + d1 * lo.y + bb0};
            *(float2*)(out + idx) = o0v;
            size_t idx2 = idx + 8 * (size_t)Sn;
            float2 xr2 = *(const float2*)(x + idx2);
            float2 o1v = {xr2.x + d0 * hi.x + bb1, xr2.y + d1 * hi.y + bb1};
            *(float2*)(out + idx2) = o1v;
        }
    }
}

// ---------------------------------------------------------------------------
extern "C" void kernel_launch(void* const* d_in, const int* in_sizes, int n_in,
                              void* d_out, int out_size) {
    const float* x  = (const float*)d_in[0];
    const float* Wq = (const float*)d_in[1];
    const float* bq = (const float*)d_in[2];
    const float* Wk = (const float*)d_in[3];
    const float* bk = (const float*)d_in[4];
    const float* Wv = (const float*)d_in[5];
    const float* bv = (const float*)d_in[6];
    const float* Wn = (const float*)d_in[7];
    const float* bn = (const float*)d_in[8];
    float* out = (float*)d_out;

    cudaFuncSetAttribute(scores_kernel,
                         cudaFuncAttributeMaxDynamicSharedMemorySize, SC_SMEM);

    wconv_kernel<<<dim3(16, 16, 4), 256>>>(Wq, Wk, Wv, Wn);
    gn_kernel<<<Bn * 32, 256>>>(x);

    proj_kernel<<<dim3(8, 8, Bn), 256>>>(bq, bk, bv);

    scores_kernel<<<dim3(4, 16, Bn), 256, SC_SMEM>>>();

    final_kernel<<<dim3(Cn / 128, Sn / 64, Bn), 256>>>(x, bn, out);
}

// round 16
// speedup vs baseline: 1.1802x; 1.1802x over previous
#include <cuda_runtime.h>
#include <cuda_fp16.h>

#define Bn 16
#define Cn 512
#define Sn 1024

// ---- scratch (no allocs allowed) ----
__device__ __half g_hn [Bn * Cn * Sn];   // [b][c][s]  (k-major for proj A)
__device__ __half g_Qt [Bn * Sn * Cn];   // [b][s][o]  (scale folded in)
__device__ __half g_Kt [Bn * Sn * Cn];   // [b][s][o]
__device__ __half g_Vt [Bn * Sn * Cn];   // [b][s][o]
__device__ __half g_Wqt[Cn * Cn];        // W^T : [out][in]
__device__ __half g_Wkt[Cn * Cn];
__device__ __half g_Wvt[Cn * Cn];
__device__ __half g_Wnt[Cn * Cn];
__device__ float  g_D  [Bn * Sn];        // diag softmax

// ---------------------------------------------------------------------------
__device__ __forceinline__ void mma_f16(unsigned c[2], const unsigned a[4],
                                        unsigned b0, unsigned b1) {
    asm volatile(
        "mma.sync.aligned.m16n8k16.row.col.f16.f16.f16.f16 "
        "{%0,%1},{%2,%3,%4,%5},{%6,%7},{%0,%1};\n"
        : "+r"(c[0]), "+r"(c[1])
        : "r"(a[0]), "r"(a[1]), "r"(a[2]), "r"(a[3]), "r"(b0), "r"(b1));
}

__device__ __forceinline__ void ldm_x4(unsigned f[4], const void* p) {
    unsigned addr = (unsigned)__cvta_generic_to_shared(p);
    asm volatile(
        "ldmatrix.sync.aligned.m8n8.x4.shared.b16 {%0,%1,%2,%3},[%4];\n"
        : "=r"(f[0]), "=r"(f[1]), "=r"(f[2]), "=r"(f[3]) : "r"(addr));
}
__device__ __forceinline__ void ldm_x4u(unsigned f[4], unsigned addr) {
    asm volatile(
        "ldmatrix.sync.aligned.m8n8.x4.shared.b16 {%0,%1,%2,%3},[%4];\n"
        : "=r"(f[0]), "=r"(f[1]), "=r"(f[2]), "=r"(f[3]) : "r"(addr));
}

__device__ __forceinline__ void cp16(void* dst, const void* src) {
    unsigned d = (unsigned)__cvta_generic_to_shared(dst);
    asm volatile("cp.async.cg.shared.global [%0], [%1], 16;\n" :: "r"(d), "l"(src));
}
__device__ __forceinline__ void cp16s(unsigned dst, const void* src) {
    asm volatile("cp.async.cg.shared.global [%0], [%1], 16;\n" :: "r"(dst), "l"(src));
}
__device__ __forceinline__ void cp_commit() {
    asm volatile("cp.async.commit_group;\n");
}
template <int N> __device__ __forceinline__ void cp_wait() {
    asm volatile("cp.async.wait_group %0;\n" :: "n"(N));
}

// ---------------------------------------------------------------------------
// Weight transpose+convert: Wt[out][in] f16 = W[in][out] fp32.
// ---------------------------------------------------------------------------
__global__ void __launch_bounds__(256) wconv_kernel(const float* __restrict__ Wq,
                                                    const float* __restrict__ Wk,
                                                    const float* __restrict__ Wv,
                                                    const float* __restrict__ Wn) {
    __shared__ float t[32][33];
    int w = blockIdx.z;
    const float* src = (w == 0) ? Wq : (w == 1) ? Wk : (w == 2) ? Wv : Wn;
    __half* dst = (w == 0) ? g_Wqt : (w == 1) ? g_Wkt : (w == 2) ? g_Wvt : g_Wnt;
    int c0 = blockIdx.x * 32, r0 = blockIdx.y * 32;
    int tx = threadIdx.x & 31, ty = threadIdx.x >> 5;
#pragma unroll
    for (int i = 0; i < 4; i++)
        t[ty + i * 8][tx] = src[(size_t)(r0 + ty + i * 8) * Cn + c0 + tx];
    __syncthreads();
#pragma unroll
    for (int i = 0; i < 4; i++)
        dst[(size_t)(c0 + ty + i * 8) * Cn + r0 + tx] = __float2half(t[tx][ty + i * 8]);
}

// ---------------------------------------------------------------------------
// GroupNorm: one block per (b, group); whole group tile in registers. -> f16
// ---------------------------------------------------------------------------
__global__ void __launch_bounds__(256) gn_kernel(const float* __restrict__ x) {
    int b = blockIdx.x >> 5, g = blockIdx.x & 31;
    size_t base = ((size_t)b * Cn + g * 16) * Sn;
    const float4* x4 = (const float4*)(x + base);
    int tid = threadIdx.x;

    float4 v[16];
    float s = 0.f, ss = 0.f;
#pragma unroll
    for (int i = 0; i < 16; i++) {
        v[i] = x4[tid + i * 256];
        s  += v[i].x + v[i].y + v[i].z + v[i].w;
        ss += v[i].x * v[i].x + v[i].y * v[i].y + v[i].z * v[i].z + v[i].w * v[i].w;
    }
    __shared__ float rs[256], rq[256];
    rs[tid] = s; rq[tid] = ss;
    __syncthreads();
    for (int off = 128; off; off >>= 1) {
        if (tid < off) { rs[tid] += rs[tid + off]; rq[tid] += rq[tid + off]; }
        __syncthreads();
    }
    const float invN = 1.f / 16384.f;
    float mean = rs[0] * invN;
    float var  = rq[0] * invN - mean * mean;
    float inv  = rsqrtf(var + 1e-5f);

    uint2* h2 = (uint2*)(g_hn + base);
#pragma unroll
    for (int i = 0; i < 16; i++) {
        __half2 p0 = __floats2half2_rn((v[i].x - mean) * inv, (v[i].y - mean) * inv);
        __half2 p1 = __floats2half2_rn((v[i].z - mean) * inv, (v[i].w - mean) * inv);
        uint2 u; u.x = *(unsigned*)&p0; u.y = *(unsigned*)&p1;
        h2[tid + i * 256] = u;
    }
}

// ---------------------------------------------------------------------------
// Fused QKV projection (HMMA): ONE block computes Q, K and V for the same
// (s0, o0) tile, sharing the A tile and A fragments. 128x64, BK=32, 8 warps.
// ---------------------------------------------------------------------------
__global__ void __launch_bounds__(256) proj_kernel(const float* __restrict__ bq,
                                                   const float* __restrict__ bk,
                                                   const float* __restrict__ bv) {
    int b = blockIdx.z;
    int s0 = blockIdx.x * 128, o0 = blockIdx.y * 64;
    const __half* A = g_hn + (size_t)b * Cn * Sn;
    const __half* Wts[3] = {g_Wqt, g_Wkt, g_Wvt};

    __shared__ __align__(16) __half As[2][32][136];     // [k][m]
    __shared__ __align__(16) __half Bs[2][3][64][40];   // [w][n][k]

    int tid = threadIdx.x, lane = tid & 31, warp = tid >> 5;
    int wm = (warp & 3) * 32, wn = (warp >> 2) * 32;

    int ra = tid >> 3, ca = (tid & 7) * 16;
    int rb = tid >> 2, cb = (tid & 3) * 8;

    int mi = lane >> 3;
    int a_kr = (lane & 7) + ((mi >> 1) << 3);
    int a_mc = (mi & 1) << 3;

    int q4 = lane >> 3, r8 = lane & 7;
    int b_ro = ((q4 >> 1) << 3) + r8, b_co = (q4 & 1) << 3;

    auto issue = [&](int c0, int st) {
        cp16(&As[st][ra][ca],     A + (size_t)(c0 + ra) * Sn + s0 + ca);
        cp16(&As[st][ra][ca + 8], A + (size_t)(c0 + ra) * Sn + s0 + ca + 8);
#pragma unroll
        for (int w = 0; w < 3; w++)
            cp16(&Bs[st][w][rb][cb], Wts[w] + (size_t)(o0 + rb) * Cn + c0 + cb);
        cp_commit();
    };
    issue(0, 0);
    issue(32, 1);

    unsigned acc[3][2][4][2] = {};
#pragma unroll 1
    for (int it = 0; it < 16; it++) {
        if (it < 14) cp_wait<1>(); else cp_wait<0>();
        __syncthreads();
        int st = it & 1;
#pragma unroll
        for (int kk = 0; kk < 32; kk += 16) {
            unsigned af[2][4];
#pragma unroll
            for (int im = 0; im < 2; im++) {
                unsigned addr = (unsigned)__cvta_generic_to_shared(
                    &As[st][kk + a_kr][wm + im * 16 + a_mc]);
                asm volatile(
                    "ldmatrix.sync.aligned.m8n8.x4.trans.shared.b16 {%0,%1,%2,%3},[%4];\n"
                    : "=r"(af[im][0]), "=r"(af[im][1]), "=r"(af[im][2]), "=r"(af[im][3])
                    : "r"(addr));
            }
#pragma unroll
            for (int w = 0; w < 3; w++) {
                unsigned bf[2][4];
#pragma unroll
                for (int jp = 0; jp < 2; jp++)
                    ldm_x4(bf[jp], &Bs[st][w][wn + jp * 16 + b_ro][kk + b_co]);
#pragma unroll
                for (int jp = 0; jp < 2; jp++)
#pragma unroll
                    for (int im = 0; im < 2; im++) {
                        mma_f16(acc[w][im][2 * jp],     af[im], bf[jp][0], bf[jp][1]);
                        mma_f16(acc[w][im][2 * jp + 1], af[im], bf[jp][2], bf[jp][3]);
                    }
            }
        }
        __syncthreads();
        if (it + 2 < 16) issue((it + 2) * 32, st);
    }

    int g = lane >> 2, t = lane & 3;
#pragma unroll
    for (int w = 0; w < 3; w++) {
        const float* bias = (w == 0) ? bq : (w == 1) ? bk : bv;
        __half* out = ((w == 0) ? g_Qt : (w == 1) ? g_Kt : g_Vt) + (size_t)b * Sn * Cn;
        const float qs = (w == 0) ? 0.04419417382415922f : 1.f;  // 512^-0.5 into Q
#pragma unroll
        for (int im = 0; im < 2; im++) {
            int m = s0 + wm + im * 16 + g;
#pragma unroll
            for (int jn = 0; jn < 4; jn++) {
                int n = o0 + wn + jn * 8 + 2 * t;
                float b0f = bias[n], b1f = bias[n + 1];
                float2 lo = __half22float2(*(__half2*)&acc[w][im][jn][0]);
                float2 hi = __half22float2(*(__half2*)&acc[w][im][jn][1]);
                __half2 v0 = __floats2half2_rn((lo.x + b0f) * qs, (lo.y + b1f) * qs);
                __half2 v1 = __floats2half2_rn((hi.x + b0f) * qs, (hi.y + b1f) * qs);
                *(unsigned*)(out + (size_t)m * Cn + n)       = *(unsigned*)&v0;
                *(unsigned*)(out + (size_t)(m + 8) * Cn + n) = *(unsigned*)&v1;
            }
        }
    }
}

// ---------------------------------------------------------------------------
// Scores + diag softmax; 512 threads, 4x4 warps, warp tile 32x32, f16 acc.
// BK=64, THREE stages, ONE barrier per iteration: loads for it+2 are issued
// right after the top barrier, targeting stage (it+2)%3 which can never
// collide with the stage being read (it%3) or the in-flight (it+1)%3.
// Dynamic smem 3 x (Q 128x144B + K 128x144B) = 110592 B -> 2 CTAs/SM.
// Block (jg, ig, b); each warp owns one 32x32 softmax group.
// ---------------------------------------------------------------------------
#define SC_TILE 18432                 // 128 rows x 144 B
#define SC_STG  (2 * SC_TILE)         // Q + K per stage
#define SC_SMEM (3 * SC_STG)          // 110592 B

__global__ void __launch_bounds__(512, 2) scores_kernel() {
    extern __shared__ char dsm_raw[];
    unsigned base_u = (unsigned)__cvta_generic_to_shared(dsm_raw);

    int b = blockIdx.z, ig = blockIdx.y, jg = blockIdx.x;
    int tid = threadIdx.x, lane = tid & 31, warp = tid >> 5;
    int ii = warp & 3, jj = warp >> 2;
    int wm = ii * 32, wn = jj * 32;

    const __half* Qb = g_Qt + (size_t)b * Sn * Cn;
    const __half* Kb = g_Kt + (size_t)b * Sn * Cn;

    int rr = tid >> 2, koff = (tid & 3) * 16;   // row 0..127, k-offset in halves
    int s1 = (rr & 31) * 32 + ig * 4 + (rr >> 5);
    int s2 = (rr & 31) * 32 + jg * 4 + (rr >> 5);
    const __half* qrow = Qb + (size_t)s1 * Cn;
    const __half* krow = Kb + (size_t)s2 * Cn;

    auto load_stage = [&](int it, int st) {
        int c0 = it * 64;
        unsigned qd = base_u + st * SC_STG + rr * 144 + koff * 2;
        cp16s(qd,      qrow + c0 + koff);
        cp16s(qd + 16, qrow + c0 + koff + 8);
        unsigned kd = qd + SC_TILE;
        cp16s(kd,      krow + c0 + koff);
        cp16s(kd + 16, krow + c0 + koff + 8);
        cp_commit();
    };
    load_stage(0, 0);
    load_stage(1, 1);

    // ldmatrix.x4 lane addressing ([row][k])
    int q4 = lane >> 3, r8 = lane & 7;
    int a_ro = ((q4 & 1) << 3) + r8, a_co = (q4 >> 1) << 3;   // A: m-rows
    int b_ro = ((q4 >> 1) << 3) + r8, b_co = (q4 & 1) << 3;   // B: n-rows

    unsigned acc[2][4][2] = {};
#pragma unroll 1
    for (int it = 0; it < 8; it++) {
        if (it < 7) cp_wait<1>(); else cp_wait<0>();
        __syncthreads();
        if (it + 2 < 8) load_stage(it + 2, (it + 2) % 3);
        int st = it % 3;
        unsigned qt = base_u + st * SC_STG;
        unsigned kt = qt + SC_TILE;
#pragma unroll
        for (int kk = 0; kk < 64; kk += 16) {
            unsigned af[2][4], bf[2][4];
#pragma unroll
            for (int im = 0; im < 2; im++)
                ldm_x4u(af[im], qt + (wm + im * 16 + a_ro) * 144 + (kk + a_co) * 2);
#pragma unroll
            for (int jp = 0; jp < 2; jp++)
                ldm_x4u(bf[jp], kt + (wn + jp * 16 + b_ro) * 144 + (kk + b_co) * 2);
#pragma unroll
            for (int jp = 0; jp < 2; jp++)
#pragma unroll
                for (int im = 0; im < 2; im++) {
                    mma_f16(acc[im][2 * jp],     af[im], bf[jp][0], bf[jp][1]);
                    mma_f16(acc[im][2 * jp + 1], af[im], bf[jp][2], bf[jp][3]);
                }
        }
    }

    // per-warp softmax over its 32x32 group (scale already folded into Q)
    float mx = -1e30f;
#pragma unroll
    for (int im = 0; im < 2; im++)
#pragma unroll
        for (int jn = 0; jn < 4; jn++)
#pragma unroll
            for (int r = 0; r < 2; r++) {
                float2 f = __half22float2(*(__half2*)&acc[im][jn][r]);
                mx = fmaxf(mx, fmaxf(f.x, f.y));
            }
#pragma unroll
    for (int off = 16; off; off >>= 1) mx = fmaxf(mx, __shfl_xor_sync(0xffffffffu, mx, off));

    float se = 0.f;
#pragma unroll
    for (int im = 0; im < 2; im++)
#pragma unroll
        for (int jn = 0; jn < 4; jn++)
#pragma unroll
            for (int r = 0; r < 2; r++) {
                float2 f = __half22float2(*(__half2*)&acc[im][jn][r]);
                se += __expf(f.x - mx) + __expf(f.y - mx);
            }
#pragma unroll
    for (int off = 16; off; off >>= 1) se += __shfl_xor_sync(0xffffffffu, se, off);

    // diag element at local (row = ig*4+ii, col = jg*4+jj)
    int rl = ig * 4 + ii, cl = jg * 4 + jj;
    int im_d = rl >> 4, rlow = rl & 15, reg_d = rlow >> 3, g_d = rlow & 7;
    int jn_d = cl >> 3, t_d = (cl & 7) >> 1, par = cl & 1;
    float cand = 0.f;
#pragma unroll
    for (int im = 0; im < 2; im++)
#pragma unroll
        for (int jn = 0; jn < 4; jn++)
#pragma unroll
            for (int r = 0; r < 2; r++)
                if (im == im_d && jn == jn_d && r == reg_d) {
                    float2 f = __half22float2(*(__half2*)&acc[im][jn][r]);
                    cand = par ? f.y : f.x;
                }
    float dv = __shfl_sync(0xffffffffu, cand, g_d * 4 + t_d);
    if (lane == 0) {
        int i = ig * 4 + ii, j = jg * 4 + jj;
        g_D[b * Sn + i * 32 + j] = __expf(dv - mx) / se;
    }
}

// ---------------------------------------------------------------------------
// Final GEMM (HMMA), f16 acc, BK=64:
// out[b][c][s] = x + D[b][s]*(sum_o Wn[o][c]*Vt[b][s][o]) + bn[c]
// ---------------------------------------------------------------------------
__global__ void __launch_bounds__(256) final_kernel(const float* __restrict__ x,
                                                    const float* __restrict__ bn,
                                                    float* __restrict__ out) {
    int b = blockIdx.z, m0 = blockIdx.x * 128, n0 = blockIdx.y * 64;
    const __half* Bsrc = g_Vt + (size_t)b * Sn * Cn;

    __shared__ __align__(16) __half As[2][128][72];  // [m][k]
    __shared__ __align__(16) __half Bs[2][64][72];   // [n][k]
    __shared__ float Ds[64];

    int tid = threadIdx.x, lane = tid & 31, warp = tid >> 5;
    int wm = (warp & 3) * 32, wn = (warp >> 2) * 32;

    int ra = tid >> 1, ca = (tid & 1) * 32;
    int rb = tid >> 2, cb = (tid & 3) * 16;

    int q4 = lane >> 3, r8 = lane & 7;
    int a_ro = ((q4 & 1) << 3) + r8, a_co = (q4 >> 1) << 3;
    int b_ro = ((q4 >> 1) << 3) + r8, b_co = (q4 & 1) << 3;

    if (tid < 64) Ds[tid] = g_D[b * Sn + n0 + tid];

    auto issue = [&](int c0, int st) {
        const __half* ar = g_Wnt + (size_t)(m0 + ra) * Cn + c0 + ca;
        cp16(&As[st][ra][ca],      ar);
        cp16(&As[st][ra][ca + 8],  ar + 8);
        cp16(&As[st][ra][ca + 16], ar + 16);
        cp16(&As[st][ra][ca + 24], ar + 24);
        const __half* br = Bsrc + (size_t)(n0 + rb) * Cn + c0 + cb;
        cp16(&Bs[st][rb][cb],     br);
        cp16(&Bs[st][rb][cb + 8], br + 8);
        cp_commit();
    };
    issue(0, 0);
    issue(64, 1);

    unsigned acc[2][4][2] = {};
#pragma unroll 1
    for (int it = 0; it < 8; it++) {
        if (it < 6) cp_wait<1>(); else cp_wait<0>();
        __syncthreads();
        int st = it & 1;
#pragma unroll
        for (int kk = 0; kk < 64; kk += 16) {
            unsigned af[2][4], bf[2][4];
#pragma unroll
            for (int im = 0; im < 2; im++)
                ldm_x4(af[im], &As[st][wm + im * 16 + a_ro][kk + a_co]);
#pragma unroll
            for (int jp = 0; jp < 2; jp++)
                ldm_x4(bf[jp], &Bs[st][wn + jp * 16 + b_ro][kk + b_co]);
#pragma unroll
            for (int jp = 0; jp < 2; jp++)
#pragma unroll
                for (int im = 0; im < 2; im++) {
                    mma_f16(acc[im][2 * jp],     af[im], bf[jp][0], bf[jp][1]);
                    mma_f16(acc[im][2 * jp + 1], af[im], bf[jp][2], bf[jp][3]);
                }
        }
        __syncthreads();
        if (it + 2 < 8) issue((it + 2) * 64, st);
    }

    int g = lane >> 2, t = lane & 3;
#pragma unroll
    for (int im = 0; im < 2; im++) {
        int m = m0 + wm + im * 16 + g;
        float bb0 = bn[m], bb1 = bn[m + 8];
#pragma unroll
        for (int jn = 0; jn < 4; jn++) {
            int n = n0 + wn + jn * 8 + 2 * t;
            float d0 = Ds[n - n0], d1 = Ds[n - n0 + 1];
            float2 lo = __half22float2(*(__half2*)&acc[im][jn][0]);
            float2 hi = __half22float2(*(__half2*)&acc[im][jn][1]);
            size_t idx = ((size_t)b * Cn + m) * Sn + n;
            float2 xr = *(const float2*)(x + idx);
            float2 o0v = {xr.x + d0 * lo.x + bb0, xr.y + d1 * lo.y + bb0};
            *(float2*)(out + idx) = o0v;
            size_t idx2 = idx + 8 * (size_t)Sn;
            float2 xr2 = *(const float2*)(x + idx2);
            float2 o1v = {xr2.x + d0 * hi.x + bb1, xr2.y + d1 * hi.y + bb1};
            *(float2*)(out + idx2) = o1v;
        }
    }
}

// ---------------------------------------------------------------------------
extern "C" void kernel_launch(void* const* d_in, const int* in_sizes, int n_in,
                              void* d_out, int out_size) {
    const float* x  = (const float*)d_in[0];
    const float* Wq = (const float*)d_in[1];
    const float* bq = (const float*)d_in[2];
    const float* Wk = (const float*)d_in[3];
    const float* bk = (const float*)d_in[4];
    const float* Wv = (const float*)d_in[5];
    const float* bv = (const float*)d_in[6];
    const float* Wn = (const float*)d_in[7];
    const float* bn = (const float*)d_in[8];
    float* out = (float*)d_out;

    cudaFuncSetAttribute(scores_kernel,
                         cudaFuncAttributeMaxDynamicSharedMemorySize, SC_SMEM);

    wconv_kernel<<<dim3(16, 16, 4), 256>>>(Wq, Wk, Wv, Wn);
    gn_kernel<<<Bn * 32, 256>>>(x);

    proj_kernel<<<dim3(8, 8, Bn), 256>>>(bq, bk, bv);

    scores_kernel<<<dim3(8, 8, Bn), 512, SC_SMEM>>>();

    final_kernel<<<dim3(Cn / 128, Sn / 64, Bn), 256>>>(x, bn, out);
}

// round 17
// speedup vs baseline: 1.2133x; 1.0280x over previous
#include <cuda_runtime.h>
#include <cuda_fp16.h>

#define Bn 16
#define Cn 512
#define Sn 1024

// ---- scratch (no allocs allowed) ----
__device__ __half g_hn [Bn * Cn * Sn];   // [b][c][s]  (k-major for proj A)
__device__ __half g_Qt [Bn * Sn * Cn];   // [b][s][o]  (scale folded in)
__device__ __half g_Kt [Bn * Sn * Cn];   // [b][s][o]
__device__ __half g_Vt [Bn * Sn * Cn];   // [b][s][o]
__device__ __half g_Wqt[Cn * Cn];        // W^T : [out][in]
__device__ __half g_Wkt[Cn * Cn];
__device__ __half g_Wvt[Cn * Cn];
__device__ __half g_Wnt[Cn * Cn];
__device__ float  g_D  [Bn * Sn];        // diag softmax

// ---------------------------------------------------------------------------
__device__ __forceinline__ void mma_f16(unsigned c[2], const unsigned a[4],
                                        unsigned b0, unsigned b1) {
    asm volatile(
        "mma.sync.aligned.m16n8k16.row.col.f16.f16.f16.f16 "
        "{%0,%1},{%2,%3,%4,%5},{%6,%7},{%0,%1};\n"
        : "+r"(c[0]), "+r"(c[1])
        : "r"(a[0]), "r"(a[1]), "r"(a[2]), "r"(a[3]), "r"(b0), "r"(b1));
}

__device__ __forceinline__ void ldm_x4u(unsigned f[4], unsigned addr) {
    asm volatile(
        "ldmatrix.sync.aligned.m8n8.x4.shared.b16 {%0,%1,%2,%3},[%4];\n"
        : "=r"(f[0]), "=r"(f[1]), "=r"(f[2]), "=r"(f[3]) : "r"(addr));
}
__device__ __forceinline__ void ldm_x4t(unsigned f[4], unsigned addr) {
    asm volatile(
        "ldmatrix.sync.aligned.m8n8.x4.trans.shared.b16 {%0,%1,%2,%3},[%4];\n"
        : "=r"(f[0]), "=r"(f[1]), "=r"(f[2]), "=r"(f[3]) : "r"(addr));
}

__device__ __forceinline__ void cp16s(unsigned dst, const void* src) {
    asm volatile("cp.async.cg.shared.global [%0], [%1], 16;\n" :: "r"(dst), "l"(src));
}
__device__ __forceinline__ void cp_commit() {
    asm volatile("cp.async.commit_group;\n");
}
template <int N> __device__ __forceinline__ void cp_wait() {
    asm volatile("cp.async.wait_group %0;\n" :: "n"(N));
}

// ---------------------------------------------------------------------------
// Weight transpose+convert: Wt[out][in] f16 = W[in][out] fp32.
// ---------------------------------------------------------------------------
__global__ void __launch_bounds__(256) wconv_kernel(const float* __restrict__ Wq,
                                                    const float* __restrict__ Wk,
                                                    const float* __restrict__ Wv,
                                                    const float* __restrict__ Wn) {
    __shared__ float t[32][33];
    int w = blockIdx.z;
    const float* src = (w == 0) ? Wq : (w == 1) ? Wk : (w == 2) ? Wv : Wn;
    __half* dst = (w == 0) ? g_Wqt : (w == 1) ? g_Wkt : (w == 2) ? g_Wvt : g_Wnt;
    int c0 = blockIdx.x * 32, r0 = blockIdx.y * 32;
    int tx = threadIdx.x & 31, ty = threadIdx.x >> 5;
#pragma unroll
    for (int i = 0; i < 4; i++)
        t[ty + i * 8][tx] = src[(size_t)(r0 + ty + i * 8) * Cn + c0 + tx];
    __syncthreads();
#pragma unroll
    for (int i = 0; i < 4; i++)
        dst[(size_t)(c0 + ty + i * 8) * Cn + r0 + tx] = __float2half(t[tx][ty + i * 8]);
}

// ---------------------------------------------------------------------------
// GroupNorm: one block per (b, group); whole group tile in registers. -> f16
// ---------------------------------------------------------------------------
__global__ void __launch_bounds__(256) gn_kernel(const float* __restrict__ x) {
    int b = blockIdx.x >> 5, g = blockIdx.x & 31;
    size_t base = ((size_t)b * Cn + g * 16) * Sn;
    const float4* x4 = (const float4*)(x + base);
    int tid = threadIdx.x;

    float4 v[16];
    float s = 0.f, ss = 0.f;
#pragma unroll
    for (int i = 0; i < 16; i++) {
        v[i] = x4[tid + i * 256];
        s  += v[i].x + v[i].y + v[i].z + v[i].w;
        ss += v[i].x * v[i].x + v[i].y * v[i].y + v[i].z * v[i].z + v[i].w * v[i].w;
    }
    __shared__ float rs[256], rq[256];
    rs[tid] = s; rq[tid] = ss;
    __syncthreads();
    for (int off = 128; off; off >>= 1) {
        if (tid < off) { rs[tid] += rs[tid + off]; rq[tid] += rq[tid + off]; }
        __syncthreads();
    }
    const float invN = 1.f / 16384.f;
    float mean = rs[0] * invN;
    float var  = rq[0] * invN - mean * mean;
    float inv  = rsqrtf(var + 1e-5f);

    uint2* h2 = (uint2*)(g_hn + base);
#pragma unroll
    for (int i = 0; i < 16; i++) {
        __half2 p0 = __floats2half2_rn((v[i].x - mean) * inv, (v[i].y - mean) * inv);
        __half2 p1 = __floats2half2_rn((v[i].z - mean) * inv, (v[i].w - mean) * inv);
        uint2 u; u.x = *(unsigned*)&p0; u.y = *(unsigned*)&p1;
        h2[tid + i * 256] = u;
    }
}

// ---------------------------------------------------------------------------
// Fused QKV projection (HMMA): ONE block computes Q, K and V for the same
// (s0, o0) tile, sharing the A tile and A fragments. 128x64, BK=32, 8 warps.
// 3-stage cp.async pipeline, ONE barrier per iteration. Dynamic smem:
//   As 3 x [32][136]h = 26112 B, Bs 3 x [3][64][40]h = 46080 B -> 70.5 KB.
// ---------------------------------------------------------------------------
#define PJ_AS_STG 8704                  // 32*136*2
#define PJ_BS_STG 15360                 // 3*64*40*2
#define PJ_BS_W   5120                  // 64*40*2
#define PJ_SMEM   (3 * (PJ_AS_STG + PJ_BS_STG))

__global__ void __launch_bounds__(256, 2) proj_kernel(const float* __restrict__ bq,
                                                      const float* __restrict__ bk,
                                                      const float* __restrict__ bv) {
    extern __shared__ char dsm_raw[];
    unsigned asb = (unsigned)__cvta_generic_to_shared(dsm_raw);
    unsigned bsb = asb + 3 * PJ_AS_STG;

    int b = blockIdx.z;
    int s0 = blockIdx.x * 128, o0 = blockIdx.y * 64;
    const __half* A = g_hn + (size_t)b * Cn * Sn;
    const __half* Wts[3] = {g_Wqt, g_Wkt, g_Wvt};

    int tid = threadIdx.x, lane = tid & 31, warp = tid >> 5;
    int wm = (warp & 3) * 32, wn = (warp >> 2) * 32;

    int ra = tid >> 3, ca = (tid & 7) * 16;   // As loader: k-row 0..31, m-col
    int rb = tid >> 2, cb = (tid & 3) * 8;    // Bs loader: n-row 0..63, k-col

    int mi = lane >> 3;
    int a_kr = (lane & 7) + ((mi >> 1) << 3);
    int a_mc = (mi & 1) << 3;

    int q4 = lane >> 3, r8 = lane & 7;
    int b_ro = ((q4 >> 1) << 3) + r8, b_co = (q4 & 1) << 3;

    auto issue = [&](int it, int st) {
        int c0 = it * 32;
        unsigned ad = asb + st * PJ_AS_STG + ra * 272 + ca * 2;
        cp16s(ad,      A + (size_t)(c0 + ra) * Sn + s0 + ca);
        cp16s(ad + 16, A + (size_t)(c0 + ra) * Sn + s0 + ca + 8);
#pragma unroll
        for (int w = 0; w < 3; w++)
            cp16s(bsb + st * PJ_BS_STG + w * PJ_BS_W + rb * 80 + cb * 2,
                  Wts[w] + (size_t)(o0 + rb) * Cn + c0 + cb);
        cp_commit();
    };
    issue(0, 0);
    issue(1, 1);

    unsigned acc[3][2][4][2] = {};
#pragma unroll 1
    for (int it = 0; it < 16; it++) {
        if (it < 15) cp_wait<1>(); else cp_wait<0>();
        __syncthreads();
        if (it + 2 < 16) issue(it + 2, (it + 2) % 3);
        int st = it % 3;
        unsigned at = asb + st * PJ_AS_STG;
        unsigned bt = bsb + st * PJ_BS_STG;
#pragma unroll
        for (int kk = 0; kk < 32; kk += 16) {
            unsigned af[2][4];
#pragma unroll
            for (int im = 0; im < 2; im++)
                ldm_x4t(af[im], at + (kk + a_kr) * 272 + (wm + im * 16 + a_mc) * 2);
#pragma unroll
            for (int w = 0; w < 3; w++) {
                unsigned bf[2][4];
#pragma unroll
                for (int jp = 0; jp < 2; jp++)
                    ldm_x4u(bf[jp], bt + w * PJ_BS_W +
                                    (wn + jp * 16 + b_ro) * 80 + (kk + b_co) * 2);
#pragma unroll
                for (int jp = 0; jp < 2; jp++)
#pragma unroll
                    for (int im = 0; im < 2; im++) {
                        mma_f16(acc[w][im][2 * jp],     af[im], bf[jp][0], bf[jp][1]);
                        mma_f16(acc[w][im][2 * jp + 1], af[im], bf[jp][2], bf[jp][3]);
                    }
            }
        }
    }

    int g = lane >> 2, t = lane & 3;
#pragma unroll
    for (int w = 0; w < 3; w++) {
        const float* bias = (w == 0) ? bq : (w == 1) ? bk : bv;
        __half* out = ((w == 0) ? g_Qt : (w == 1) ? g_Kt : g_Vt) + (size_t)b * Sn * Cn;
        const float qs = (w == 0) ? 0.04419417382415922f : 1.f;  // 512^-0.5 into Q
#pragma unroll
        for (int im = 0; im < 2; im++) {
            int m = s0 + wm + im * 16 + g;
#pragma unroll
            for (int jn = 0; jn < 4; jn++) {
                int n = o0 + wn + jn * 8 + 2 * t;
                float b0f = bias[n], b1f = bias[n + 1];
                float2 lo = __half22float2(*(__half2*)&acc[w][im][jn][0]);
                float2 hi = __half22float2(*(__half2*)&acc[w][im][jn][1]);
                __half2 v0 = __floats2half2_rn((lo.x + b0f) * qs, (lo.y + b1f) * qs);
                __half2 v1 = __floats2half2_rn((hi.x + b0f) * qs, (hi.y + b1f) * qs);
                *(unsigned*)(out + (size_t)m * Cn + n)       = *(unsigned*)&v0;
                *(unsigned*)(out + (size_t)(m + 8) * Cn + n) = *(unsigned*)&v1;
            }
        }
    }
}

// ---------------------------------------------------------------------------
// Scores + diag softmax; 512 threads, 4x4 warps, warp tile 32x32, f16 acc.
// BK=64, THREE stages, ONE barrier per iteration (R15 structure).
// Dynamic smem 3 x (Q 128x144B + K 128x144B) = 110592 B -> 2 CTAs/SM.
// ---------------------------------------------------------------------------
#define SC_TILE 18432                 // 128 rows x 144 B
#define SC_STG  (2 * SC_TILE)         // Q + K per stage
#define SC_SMEM (3 * SC_STG)          // 110592 B

__global__ void __launch_bounds__(512, 2) scores_kernel() {
    extern __shared__ char dsm_raw[];
    unsigned base_u = (unsigned)__cvta_generic_to_shared(dsm_raw);

    int b = blockIdx.z, ig = blockIdx.y, jg = blockIdx.x;
    int tid = threadIdx.x, lane = tid & 31, warp = tid >> 5;
    int ii = warp & 3, jj = warp >> 2;
    int wm = ii * 32, wn = jj * 32;

    const __half* Qb = g_Qt + (size_t)b * Sn * Cn;
    const __half* Kb = g_Kt + (size_t)b * Sn * Cn;

    int rr = tid >> 2, koff = (tid & 3) * 16;
    int s1 = (rr & 31) * 32 + ig * 4 + (rr >> 5);
    int s2 = (rr & 31) * 32 + jg * 4 + (rr >> 5);
    const __half* qrow = Qb + (size_t)s1 * Cn;
    const __half* krow = Kb + (size_t)s2 * Cn;

    auto load_stage = [&](int it, int st) {
        int c0 = it * 64;
        unsigned qd = base_u + st * SC_STG + rr * 144 + koff * 2;
        cp16s(qd,      qrow + c0 + koff);
        cp16s(qd + 16, qrow + c0 + koff + 8);
        unsigned kd = qd + SC_TILE;
        cp16s(kd,      krow + c0 + koff);
        cp16s(kd + 16, krow + c0 + koff + 8);
        cp_commit();
    };
    load_stage(0, 0);
    load_stage(1, 1);

    int q4 = lane >> 3, r8 = lane & 7;
    int a_ro = ((q4 & 1) << 3) + r8, a_co = (q4 >> 1) << 3;
    int b_ro = ((q4 >> 1) << 3) + r8, b_co = (q4 & 1) << 3;

    unsigned acc[2][4][2] = {};
#pragma unroll 1
    for (int it = 0; it < 8; it++) {
        if (it < 7) cp_wait<1>(); else cp_wait<0>();
        __syncthreads();
        if (it + 2 < 8) load_stage(it + 2, (it + 2) % 3);
        int st = it % 3;
        unsigned qt = base_u + st * SC_STG;
        unsigned kt = qt + SC_TILE;
#pragma unroll
        for (int kk = 0; kk < 64; kk += 16) {
            unsigned af[2][4], bf[2][4];
#pragma unroll
            for (int im = 0; im < 2; im++)
                ldm_x4u(af[im], qt + (wm + im * 16 + a_ro) * 144 + (kk + a_co) * 2);
#pragma unroll
            for (int jp = 0; jp < 2; jp++)
                ldm_x4u(bf[jp], kt + (wn + jp * 16 + b_ro) * 144 + (kk + b_co) * 2);
#pragma unroll
            for (int jp = 0; jp < 2; jp++)
#pragma unroll
                for (int im = 0; im < 2; im++) {
                    mma_f16(acc[im][2 * jp],     af[im], bf[jp][0], bf[jp][1]);
                    mma_f16(acc[im][2 * jp + 1], af[im], bf[jp][2], bf[jp][3]);
                }
        }
    }

    // per-warp softmax over its 32x32 group (scale already folded into Q)
    float mx = -1e30f;
#pragma unroll
    for (int im = 0; im < 2; im++)
#pragma unroll
        for (int jn = 0; jn < 4; jn++)
#pragma unroll
            for (int r = 0; r < 2; r++) {
                float2 f = __half22float2(*(__half2*)&acc[im][jn][r]);
                mx = fmaxf(mx, fmaxf(f.x, f.y));
            }
#pragma unroll
    for (int off = 16; off; off >>= 1) mx = fmaxf(mx, __shfl_xor_sync(0xffffffffu, mx, off));

    float se = 0.f;
#pragma unroll
    for (int im = 0; im < 2; im++)
#pragma unroll
        for (int jn = 0; jn < 4; jn++)
#pragma unroll
            for (int r = 0; r < 2; r++) {
                float2 f = __half22float2(*(__half2*)&acc[im][jn][r]);
                se += __expf(f.x - mx) + __expf(f.y - mx);
            }
#pragma unroll
    for (int off = 16; off; off >>= 1) se += __shfl_xor_sync(0xffffffffu, se, off);

    int rl = ig * 4 + ii, cl = jg * 4 + jj;
    int im_d = rl >> 4, rlow = rl & 15, reg_d = rlow >> 3, g_d = rlow & 7;
    int jn_d = cl >> 3, t_d = (cl & 7) >> 1, par = cl & 1;
    float cand = 0.f;
#pragma unroll
    for (int im = 0; im < 2; im++)
#pragma unroll
        for (int jn = 0; jn < 4; jn++)
#pragma unroll
            for (int r = 0; r < 2; r++)
                if (im == im_d && jn == jn_d && r == reg_d) {
                    float2 f = __half22float2(*(__half2*)&acc[im][jn][r]);
                    cand = par ? f.y : f.x;
                }
    float dv = __shfl_sync(0xffffffffu, cand, g_d * 4 + t_d);
    if (lane == 0) {
        int i = ig * 4 + ii, j = jg * 4 + jj;
        g_D[b * Sn + i * 32 + j] = __expf(dv - mx) / se;
    }
}

// ---------------------------------------------------------------------------
// Final GEMM (HMMA), f16 acc, BK=64, 3-stage single-barrier pipeline:
// out[b][c][s] = x + D[b][s]*(sum_o Wn[o][c]*Vt[b][s][o]) + bn[c]
// Dynamic smem: As 3 x [128][72]h = 55296 B, Bs 3 x [64][72]h = 27648 B.
// ---------------------------------------------------------------------------
#define FN_AS_STG 18432                 // 128*144
#define FN_BS_STG 9216                  // 64*144
#define FN_SMEM   (3 * (FN_AS_STG + FN_BS_STG))

__global__ void __launch_bounds__(256, 2) final_kernel(const float* __restrict__ x,
                                                       const float* __restrict__ bn,
                                                       float* __restrict__ out) {
    extern __shared__ char dsm_raw[];
    unsigned asb = (unsigned)__cvta_generic_to_shared(dsm_raw);
    unsigned bsb = asb + 3 * FN_AS_STG;
    __shared__ float Ds[64];

    int b = blockIdx.z, m0 = blockIdx.x * 128, n0 = blockIdx.y * 64;
    const __half* Bsrc = g_Vt + (size_t)b * Sn * Cn;

    int tid = threadIdx.x, lane = tid & 31, warp = tid >> 5;
    int wm = (warp & 3) * 32, wn = (warp >> 2) * 32;

    int ra = tid >> 1, ca = (tid & 1) * 32;
    int rb = tid >> 2, cb = (tid & 3) * 16;

    int q4 = lane >> 3, r8 = lane & 7;
    int a_ro = ((q4 & 1) << 3) + r8, a_co = (q4 >> 1) << 3;
    int b_ro = ((q4 >> 1) << 3) + r8, b_co = (q4 & 1) << 3;

    if (tid < 64) Ds[tid] = g_D[b * Sn + n0 + tid];

    auto issue = [&](int it, int st) {
        int c0 = it * 64;
        const __half* ar = g_Wnt + (size_t)(m0 + ra) * Cn + c0 + ca;
        unsigned ad = asb + st * FN_AS_STG + ra * 144 + ca * 2;
        cp16s(ad,      ar);
        cp16s(ad + 16, ar + 8);
        cp16s(ad + 32, ar + 16);
        cp16s(ad + 48, ar + 24);
        const __half* br = Bsrc + (size_t)(n0 + rb) * Cn + c0 + cb;
        unsigned bd = bsb + st * FN_BS_STG + rb * 144 + cb * 2;
        cp16s(bd,      br);
        cp16s(bd + 16, br + 8);
        cp_commit();
    };
    issue(0, 0);
    issue(1, 1);

    unsigned acc[2][4][2] = {};
#pragma unroll 1
    for (int it = 0; it < 8; it++) {
        if (it < 7) cp_wait<1>(); else cp_wait<0>();
        __syncthreads();
        if (it + 2 < 8) issue(it + 2, (it + 2) % 3);
        int st = it % 3;
        unsigned at = asb + st * FN_AS_STG;
        unsigned bt = bsb + st * FN_BS_STG;
#pragma unroll
        for (int kk = 0; kk < 64; kk += 16) {
            unsigned af[2][4], bf[2][4];
#pragma unroll
            for (int im = 0; im < 2; im++)
                ldm_x4u(af[im], at + (wm + im * 16 + a_ro) * 144 + (kk + a_co) * 2);
#pragma unroll
            for (int jp = 0; jp < 2; jp++)
                ldm_x4u(bf[jp], bt + (wn + jp * 16 + b_ro) * 144 + (kk + b_co) * 2);
#pragma unroll
            for (int jp = 0; jp < 2; jp++)
#pragma unroll
                for (int im = 0; im < 2; im++) {
                    mma_f16(acc[im][2 * jp],     af[im], bf[jp][0], bf[jp][1]);
                    mma_f16(acc[im][2 * jp + 1], af[im], bf[jp][2], bf[jp][3]);
                }
        }
    }

    int g = lane >> 2, t = lane & 3;
#pragma unroll
    for (int im = 0; im < 2; im++) {
        int m = m0 + wm + im * 16 + g;
        float bb0 = bn[m], bb1 = bn[m + 8];
#pragma unroll
        for (int jn = 0; jn < 4; jn++) {
            int n = n0 + wn + jn * 8 + 2 * t;
            float d0 = Ds[n - n0], d1 = Ds[n - n0 + 1];
            float2 lo = __half22float2(*(__half2*)&acc[im][jn][0]);
            float2 hi = __half22float2(*(__half2*)&acc[im][jn][1]);
            size_t idx = ((size_t)b * Cn + m) * Sn + n;
            float2 xr = *(const float2*)(x + idx);
            float2 o0v = {xr.x + d0 * lo.x + bb0, xr.y + d1 * lo.y + bb0};
            *(float2*)(out + idx) = o0v;
            size_t idx2 = idx + 8 * (size_t)Sn;
            float2 xr2 = *(const float2*)(x + idx2);
            float2 o1v = {xr2.x + d0 * hi.x + bb1, xr2.y + d1 * hi.y + bb1};
            *(float2*)(out + idx2) = o1v;
        }
    }
}

// ---------------------------------------------------------------------------
extern "C" void kernel_launch(void* const* d_in, const int* in_sizes, int n_in,
                              void* d_out, int out_size) {
    const float* x  = (const float*)d_in[0];
    const float* Wq = (const float*)d_in[1];
    const float* bq = (const float*)d_in[2];
    const float* Wk = (const float*)d_in[3];
    const float* bk = (const float*)d_in[4];
    const float* Wv = (const float*)d_in[5];
    const float* bv = (const float*)d_in[6];
    const float* Wn = (const float*)d_in[7];
    const float* bn = (const float*)d_in[8];
    float* out = (float*)d_out;

    cudaFuncSetAttribute(scores_kernel,
                         cudaFuncAttributeMaxDynamicSharedMemorySize, SC_SMEM);
    cudaFuncSetAttribute(proj_kernel,
                         cudaFuncAttributeMaxDynamicSharedMemorySize, PJ_SMEM);
    cudaFuncSetAttribute(final_kernel,
                         cudaFuncAttributeMaxDynamicSharedMemorySize, FN_SMEM);

    wconv_kernel<<<dim3(16, 16, 4), 256>>>(Wq, Wk, Wv, Wn);
    gn_kernel<<<Bn * 32, 256>>>(x);

    proj_kernel<<<dim3(8, 8, Bn), 256, PJ_SMEM>>>(bq, bk, bv);

    scores_kernel<<<dim3(8, 8, Bn), 512, SC_SMEM>>>();

    final_kernel<<<dim3(Cn / 128, Sn / 64, Bn), 256, FN_SMEM>>>(x, bn, out);
}